// round 3
// baseline (speedup 1.0000x reference)
#include <cuda_runtime.h>
#include <cfloat>

#define BB 256
#define TT 512
#define KK 128
#define TRP 132   // padded transposed-transitions row stride (floats)

// Scratch (__device__ globals only — no runtime allocation)
__device__ float g_states[(size_t)BB * TT * KK];   // 64 MiB Viterbi states
__device__ int   g_order[BB];                      // rank -> batch

// ---------------------------------------------------------------------------
// Rank batches by descending length. CTA i handles ranks 2i and 2i+1
// (adjacent ranks => near-equal lengths => minimal paired-loop waste).
// ---------------------------------------------------------------------------
__global__ void order_kernel(const int* __restrict__ lens)
{
    __shared__ int sl[BB];
    const int b = threadIdx.x;
    sl[b] = lens[b];
    __syncthreads();
    const int L = sl[b];
    int r = 0;
    #pragma unroll 8
    for (int i = 0; i < BB; ++i) {
        int Li = sl[i];
        r += (Li > L) || (Li == L && i < b);
    }
    g_order[r] = b;
}

// ---------------------------------------------------------------------------
// Packed f32x2 helpers (sm_103a)
// ---------------------------------------------------------------------------
__device__ __forceinline__ unsigned long long addx2(unsigned long long a,
                                                    unsigned long long b) {
    unsigned long long r;
    asm("add.rn.f32x2 %0, %1, %2;" : "=l"(r) : "l"(a), "l"(b));
    return r;
}
__device__ __forceinline__ float2 unpk(unsigned long long v) {
    float2 r;
    asm("mov.b64 {%0, %1}, %2;" : "=f"(r.x), "=f"(r.y) : "l"(v));
    return r;
}
__device__ __forceinline__ unsigned long long pk(float lo, float hi) {
    unsigned long long r;
    asm("mov.b64 %0, {%1, %2};" : "=l"(r) : "f"(lo), "f"(hi));
    return r;
}

// ---------------------------------------------------------------------------
// Backtrace helpers (warp-uniform argmax, first-index tie-break)
// ---------------------------------------------------------------------------
__device__ __forceinline__ unsigned redux_max_u32(unsigned v) {
    unsigned r;
    asm("redux.sync.max.u32 %0, %1, 0xffffffff;" : "=r"(r) : "r"(v));
    return r;
}
__device__ __forceinline__ unsigned redux_min_u32(unsigned v) {
    unsigned r;
    asm("redux.sync.min.u32 %0, %1, 0xffffffff;" : "=r"(r) : "r"(v));
    return r;
}
__device__ __forceinline__ unsigned fkey(float f) {
    unsigned u = __float_as_uint(f);
    return u ^ ((unsigned)((int)u >> 31) | 0x80000000u);
}
__device__ __forceinline__ int argmax128(float4 v, int l)
{
    unsigned k0 = fkey(v.x), k1 = fkey(v.y), k2 = fkey(v.z), k3 = fkey(v.w);
    unsigned km = max(max(k0, k1), max(k2, k3));
    unsigned M  = redux_max_u32(km);
    unsigned il = 0xFFFFFFFFu;
    if (k3 == M) il = 4 * l + 3;
    if (k2 == M) il = 4 * l + 2;
    if (k1 == M) il = 4 * l + 1;
    if (k0 == M) il = 4 * l + 0;
    return (int)redux_min_u32(il);
}

__device__ __forceinline__ void bt_step(float4 cur, const float* __restrict__ s_tr,
                                        int& tag, float* __restrict__ outrow,
                                        int l, bool addtr)
{
    if (addtr) {
        float4 tc = *reinterpret_cast<const float4*>(&s_tr[tag * TRP + 4 * l]);
        cur.x += tc.x; cur.y += tc.y; cur.z += tc.z; cur.w += tc.w;
    }
    tag = argmax128(cur, l);
    float4 r;
    r.x = (4 * l + 0 == tag) ? 1.0f : 0.0f;
    r.y = (4 * l + 1 == tag) ? 1.0f : 0.0f;
    r.z = (4 * l + 2 == tag) ? 1.0f : 0.0f;
    r.w = (4 * l + 3 == tag) ? 1.0f : 0.0f;
    reinterpret_cast<float4*>(outrow)[l] = r;
}

// ---------------------------------------------------------------------------
// Fused Viterbi: one CTA = TWO batches (rank 2*bid, 2*bid+1). 256 threads,
// half-block per batch. Thread (h, j) owns output tag j of batch h.
// Transitions column j live in packed-f32x2 registers.
// ---------------------------------------------------------------------------
__global__ void __launch_bounds__(256, 1) crf_kernel(
    const float* __restrict__ pot,
    const float* __restrict__ trans,
    const int*   __restrict__ lens,
    float*       __restrict__ out)
{
    extern __shared__ float sm[];
    float* s_tr = sm;                  // KK*TRP: transposed transitions
    float* s_stA = sm + KK * TRP;      // 2*KK ping-pong, batch A
    float* s_stB = s_stA + 2 * KK;     // 2*KK ping-pong, batch B

    const int tid = threadIdx.x;
    const int h   = tid >> 7;          // 0 = batch A, 1 = batch B
    const int j   = tid & 127;

    const int bA = g_order[blockIdx.x * 2 + 0];
    const int bB = g_order[blockIdx.x * 2 + 1];
    const int lenA = lens[bA];
    const int lenB = lens[bB];
    const int b    = h ? bB : bA;
    const int len  = h ? lenB : lenA;
    const int tmax = max(lenA, lenB);
    const size_t base = (size_t)b * TT * KK;
    float* st = h ? s_stB : s_stA;

    // Load transitions column j (packed pairs); half A stages transposed copy
    // in smem for the backtrace.
    unsigned long long ad[64];
    #pragma unroll
    for (int q = 0; q < 32; ++q) {
        float v0 = trans[(4 * q + 0) * KK + j];
        float v1 = trans[(4 * q + 1) * KK + j];
        float v2 = trans[(4 * q + 2) * KK + j];
        float v3 = trans[(4 * q + 3) * KK + j];
        ad[2 * q + 0] = pk(v0, v1);
        ad[2 * q + 1] = pk(v2, v3);
        if (h == 0)
            *reinterpret_cast<float4*>(&s_tr[j * TRP + 4 * q]) = make_float4(v0, v1, v2, v3);
    }

    float s0 = pot[base + j];
    st[j] = s0;
    g_states[base + j] = s0;
    __syncthreads();

    // ---- forward Viterbi (both batches in lockstep; near-equal lengths) ----
    int p = 0;
    for (int t = 1; t < tmax; ++t) {
        if (t < len) {   // warp-uniform (whole half shares len)
            float x = pot[base + (size_t)t * KK + j];
            const ulonglong2* sp = reinterpret_cast<const ulonglong2*>(st + p * KK);
            float m0 = -FLT_MAX, m1 = -FLT_MAX, m2 = -FLT_MAX, m3 = -FLT_MAX;
            float m4 = -FLT_MAX, m5 = -FLT_MAX, m6 = -FLT_MAX, m7 = -FLT_MAX;
            #pragma unroll
            for (int q = 0; q < 32; q += 2) {
                ulonglong2 sa = sp[q];                // broadcast LDS.128
                float2 u0 = unpk(addx2(sa.x, ad[2 * q + 0]));
                float2 u1 = unpk(addx2(sa.y, ad[2 * q + 1]));
                m0 = fmaxf(m0, u0.x);
                m1 = fmaxf(m1, u0.y);
                m2 = fmaxf(m2, u1.x);
                m3 = fmaxf(m3, u1.y);
                ulonglong2 sb = sp[q + 1];
                float2 u2 = unpk(addx2(sb.x, ad[2 * q + 2]));
                float2 u3 = unpk(addx2(sb.y, ad[2 * q + 3]));
                m4 = fmaxf(m4, u2.x);
                m5 = fmaxf(m5, u2.y);
                m6 = fmaxf(m6, u3.x);
                m7 = fmaxf(m7, u3.y);
            }
            float ma = fmaxf(fmaxf(m0, m1), fmaxf(m2, m3));
            float mb = fmaxf(fmaxf(m4, m5), fmaxf(m6, m7));
            float ns = x + fmaxf(ma, mb);
            st[(p ^ 1) * KK + j] = ns;
            g_states[base + (size_t)t * KK + j] = ns;
        }
        __syncthreads();
        p ^= 1;
    }

    // ---- epilogue ----
    const int w = tid >> 5;            // warp id 0..7 (0-3 batch A, 4-7 batch B)
    const int l = tid & 31;

    if ((w & 3) != 0) {
        // 3 warps per batch: one-hot tag-0 rows for t >= len
        const int total = (TT - len) * 32;
        for (int idx = (w & 3) * 32 + l - 32; idx < total; idx += 96) {
            int r = len + (idx >> 5);
            int c = idx & 31;
            float4 v = make_float4(c == 0 ? 1.0f : 0.0f, 0.0f, 0.0f, 0.0f);
            reinterpret_cast<float4*>(out + base + (size_t)r * KK)[c] = v;
        }
        return;
    }

    // warps 0 and 4: backtrace own batch
    auto LDst = [&](int t) -> float4 {
        if (t < 0) return make_float4(0.f, 0.f, 0.f, 0.f);
        return reinterpret_cast<const float4*>(&g_states[base + (size_t)t * KK])[l];
    };
    float* const ob = out + base;

    int tag = 0;
    float4 c0 = LDst(len - 1);
    int t = len - 2;
    float4 p0 = LDst(t), p1 = LDst(t - 1), p2 = LDst(t - 2), p3 = LDst(t - 3);

    bt_step(c0, s_tr, tag, ob + (size_t)(len - 1) * KK, l, false);

    while (t >= 3) {
        bt_step(p0, s_tr, tag, ob + (size_t)(t    ) * KK, l, true);  p0 = LDst(t - 4);
        bt_step(p1, s_tr, tag, ob + (size_t)(t - 1) * KK, l, true);  p1 = LDst(t - 5);
        bt_step(p2, s_tr, tag, ob + (size_t)(t - 2) * KK, l, true);  p2 = LDst(t - 6);
        bt_step(p3, s_tr, tag, ob + (size_t)(t - 3) * KK, l, true);  p3 = LDst(t - 7);
        t -= 4;
    }
    if (t >= 0) bt_step(p0, s_tr, tag, ob + (size_t)(t    ) * KK, l, true);
    if (t >= 1) bt_step(p1, s_tr, tag, ob + (size_t)(t - 1) * KK, l, true);
    if (t >= 2) bt_step(p2, s_tr, tag, ob + (size_t)(t - 2) * KK, l, true);
}

// ---------------------------------------------------------------------------
extern "C" void kernel_launch(void* const* d_in, const int* in_sizes, int n_in,
                              void* d_out, int out_size)
{
    const float* pot   = (const float*)d_in[0];   // (B,T,K) f32
    const float* trans = (const float*)d_in[1];   // (K,K)   f32
    const int*   lens  = (const int*)  d_in[2];   // (B,)    i32
    float* out = (float*)d_out;                   // (B,T,K) f32

    const int smem = (KK * TRP + 4 * KK) * (int)sizeof(float);   // 69,632 B
    cudaFuncSetAttribute(crf_kernel, cudaFuncAttributeMaxDynamicSharedMemorySize, smem);

    order_kernel<<<1, BB>>>(lens);
    crf_kernel<<<BB / 2, 256, smem>>>(pot, trans, lens, out);
}

// round 4
// speedup vs baseline: 1.1126x; 1.1126x over previous
#include <cuda_runtime.h>
#include <cfloat>

#define BB 256
#define TT 512
#define KK 128
#define TRP 132   // padded transposed-transitions row stride (floats)

// Scratch (__device__ globals only — no runtime allocation)
__device__ float g_states[(size_t)BB * TT * KK];   // 64 MiB Viterbi states
__device__ int   g_order[BB];                      // bid -> batch

// ---------------------------------------------------------------------------
// Rank batches by descending length; map so that bid r (r<148) and bid 403-r
// land on the same SM (classic placement): long batches pair with short ones.
// ---------------------------------------------------------------------------
__global__ void order_kernel(const int* __restrict__ lens)
{
    __shared__ int sl[BB];
    const int b = threadIdx.x;
    sl[b] = lens[b];
    __syncthreads();
    const int L = sl[b];
    int r = 0;
    #pragma unroll 8
    for (int i = 0; i < BB; ++i) {
        int Li = sl[i];
        r += (Li > L) || (Li == L && i < b);
    }
    g_order[(r < 148) ? r : (403 - r)] = b;
}

// ---------------------------------------------------------------------------
// Packed f32x2 helpers (sm_103a; compiled fine in prior round)
// ---------------------------------------------------------------------------
__device__ __forceinline__ unsigned long long addx2(unsigned long long a,
                                                    unsigned long long b) {
    unsigned long long r;
    asm("add.rn.f32x2 %0, %1, %2;" : "=l"(r) : "l"(a), "l"(b));
    return r;
}
__device__ __forceinline__ float2 unpk(unsigned long long v) {
    float2 r;
    asm("mov.b64 {%0, %1}, %2;" : "=f"(r.x), "=f"(r.y) : "l"(v));
    return r;
}
__device__ __forceinline__ unsigned long long pk(float lo, float hi) {
    unsigned long long r;
    asm("mov.b64 %0, {%1, %2};" : "=l"(r) : "f"(lo), "f"(hi));
    return r;
}

// ---------------------------------------------------------------------------
// Backtrace helpers (warp-uniform argmax, first-index tie-break)
// ---------------------------------------------------------------------------
__device__ __forceinline__ unsigned redux_max_u32(unsigned v) {
    unsigned r;
    asm("redux.sync.max.u32 %0, %1, 0xffffffff;" : "=r"(r) : "r"(v));
    return r;
}
__device__ __forceinline__ unsigned redux_min_u32(unsigned v) {
    unsigned r;
    asm("redux.sync.min.u32 %0, %1, 0xffffffff;" : "=r"(r) : "r"(v));
    return r;
}
__device__ __forceinline__ unsigned fkey(float f) {
    unsigned u = __float_as_uint(f);
    return u ^ ((unsigned)((int)u >> 31) | 0x80000000u);
}
__device__ __forceinline__ int argmax128(float4 v, int l)
{
    unsigned k0 = fkey(v.x), k1 = fkey(v.y), k2 = fkey(v.z), k3 = fkey(v.w);
    unsigned km = max(max(k0, k1), max(k2, k3));
    unsigned M  = redux_max_u32(km);
    unsigned il = 0xFFFFFFFFu;
    if (k3 == M) il = 4 * l + 3;
    if (k2 == M) il = 4 * l + 2;
    if (k1 == M) il = 4 * l + 1;
    if (k0 == M) il = 4 * l + 0;
    return (int)redux_min_u32(il);
}

__device__ __forceinline__ void bt_step(float4 cur, const float* __restrict__ s_tr,
                                        int& tag, float* __restrict__ outrow,
                                        int l, bool addtr)
{
    if (addtr) {
        float4 tc = *reinterpret_cast<const float4*>(&s_tr[tag * TRP + 4 * l]);
        cur.x += tc.x; cur.y += tc.y; cur.z += tc.z; cur.w += tc.w;
    }
    tag = argmax128(cur, l);
    float4 r;
    r.x = (4 * l + 0 == tag) ? 1.0f : 0.0f;
    r.y = (4 * l + 1 == tag) ? 1.0f : 0.0f;
    r.z = (4 * l + 2 == tag) ? 1.0f : 0.0f;
    r.w = (4 * l + 3 == tag) ? 1.0f : 0.0f;
    reinterpret_cast<float4*>(outrow)[l] = r;
}

// ---------------------------------------------------------------------------
// Fused Viterbi: one CTA = one batch, 256 threads. Thread (h, j) computes the
// partial max over i in [64h, 64h+64) for output tag j; halves combine via a
// small smem buffer. Transitions half-column in packed f32x2 registers.
// ---------------------------------------------------------------------------
__global__ void __launch_bounds__(256, 2) crf_kernel(
    const float* __restrict__ pot,
    const float* __restrict__ trans,
    const int*   __restrict__ lens,
    float*       __restrict__ out)
{
    extern __shared__ float sm[];
    float* s_tr  = sm;                  // KK*TRP: transposed transitions (backtrace)
    float* s_st  = sm + KK * TRP;       // 2*KK ping-pong state
    float* s_pt  = s_st + 2 * KK;       // KK partial buffer (half-1 partials)

    const int tid = threadIdx.x;
    const int h   = tid >> 7;           // i-range half
    const int j   = tid & 127;          // output tag

    const int b   = g_order[blockIdx.x];
    const int len = lens[b];
    const size_t base = (size_t)b * TT * KK;

    // Transitions for i in [64h, 64h+64), column j -> 32 packed u64 registers.
    // Half 0 also stages the full transposed copy in smem for the backtrace.
    unsigned long long ad[32];
    {
        const int i0 = h * 64;
        #pragma unroll
        for (int q = 0; q < 16; ++q) {
            float v0 = trans[(i0 + 4 * q + 0) * KK + j];
            float v1 = trans[(i0 + 4 * q + 1) * KK + j];
            float v2 = trans[(i0 + 4 * q + 2) * KK + j];
            float v3 = trans[(i0 + 4 * q + 3) * KK + j];
            ad[2 * q + 0] = pk(v0, v1);
            ad[2 * q + 1] = pk(v2, v3);
            // stage transposed rows: half h covers columns i0..i0+63 of row j
            *reinterpret_cast<float4*>(&s_tr[j * TRP + i0 + 4 * q]) =
                make_float4(v0, v1, v2, v3);
        }
    }

    if (h == 0) {
        float s0 = pot[base + j];
        s_st[j] = s0;
        g_states[base + j] = s0;
    }
    __syncthreads();

    // ---- forward Viterbi ----
    float xpre = (len > 1 && h == 0) ? pot[base + (size_t)1 * KK + j] : 0.0f;
    int p = 0;
    for (int t = 1; t < len; ++t) {
        float x = xpre;
        if (h == 0) {
            int tn = (t + 1 < len) ? (t + 1) : t;
            xpre = pot[base + (size_t)tn * KK + j];     // prefetch next step
        }

        const ulonglong2* sp =
            reinterpret_cast<const ulonglong2*>(s_st + p * KK + h * 64);
        float m0 = -FLT_MAX, m1 = -FLT_MAX, m2 = -FLT_MAX, m3 = -FLT_MAX;
        float m4 = -FLT_MAX, m5 = -FLT_MAX, m6 = -FLT_MAX, m7 = -FLT_MAX;
        #pragma unroll
        for (int q = 0; q < 16; q += 2) {
            ulonglong2 sa = sp[q];                      // broadcast LDS.128
            float2 u0 = unpk(addx2(sa.x, ad[2 * q + 0]));
            float2 u1 = unpk(addx2(sa.y, ad[2 * q + 1]));
            m0 = fmaxf(m0, u0.x);
            m1 = fmaxf(m1, u0.y);
            m2 = fmaxf(m2, u1.x);
            m3 = fmaxf(m3, u1.y);
            ulonglong2 sb = sp[q + 1];
            float2 u2 = unpk(addx2(sb.x, ad[2 * q + 2]));
            float2 u3 = unpk(addx2(sb.y, ad[2 * q + 3]));
            m4 = fmaxf(m4, u2.x);
            m5 = fmaxf(m5, u2.y);
            m6 = fmaxf(m6, u3.x);
            m7 = fmaxf(m7, u3.y);
        }
        float pm = fmaxf(fmaxf(fmaxf(m0, m1), fmaxf(m2, m3)),
                         fmaxf(fmaxf(m4, m5), fmaxf(m6, m7)));

        if (h) s_pt[j] = pm;
        __syncthreads();
        if (!h) {
            float ns = x + fmaxf(pm, s_pt[j]);
            s_st[(p ^ 1) * KK + j] = ns;
            g_states[base + (size_t)t * KK + j] = ns;
        }
        __syncthreads();
        p ^= 1;
    }

    // ---- epilogue: warp 0 backtraces; warps 1-7 write tag-0 rows >= len ----
    const int w = tid >> 5;
    const int l = tid & 31;

    if (w != 0) {
        const int total = (TT - len) * 32;
        for (int idx = (w - 1) * 32 + l; idx < total; idx += 224) {
            int r = len + (idx >> 5);
            int c = idx & 31;
            float4 v = make_float4(c == 0 ? 1.0f : 0.0f, 0.0f, 0.0f, 0.0f);
            reinterpret_cast<float4*>(out + base + (size_t)r * KK)[c] = v;
        }
        return;
    }

    auto LDst = [&](int t) -> float4 {
        if (t < 0) return make_float4(0.f, 0.f, 0.f, 0.f);
        return reinterpret_cast<const float4*>(&g_states[base + (size_t)t * KK])[l];
    };
    float* const ob = out + base;

    int tag = 0;
    float4 c0 = LDst(len - 1);
    int t = len - 2;
    float4 p0 = LDst(t), p1 = LDst(t - 1), p2 = LDst(t - 2), p3 = LDst(t - 3);

    bt_step(c0, s_tr, tag, ob + (size_t)(len - 1) * KK, l, false);

    while (t >= 3) {
        bt_step(p0, s_tr, tag, ob + (size_t)(t    ) * KK, l, true);  p0 = LDst(t - 4);
        bt_step(p1, s_tr, tag, ob + (size_t)(t - 1) * KK, l, true);  p1 = LDst(t - 5);
        bt_step(p2, s_tr, tag, ob + (size_t)(t - 2) * KK, l, true);  p2 = LDst(t - 6);
        bt_step(p3, s_tr, tag, ob + (size_t)(t - 3) * KK, l, true);  p3 = LDst(t - 7);
        t -= 4;
    }
    if (t >= 0) bt_step(p0, s_tr, tag, ob + (size_t)(t    ) * KK, l, true);
    if (t >= 1) bt_step(p1, s_tr, tag, ob + (size_t)(t - 1) * KK, l, true);
    if (t >= 2) bt_step(p2, s_tr, tag, ob + (size_t)(t - 2) * KK, l, true);
}

// ---------------------------------------------------------------------------
extern "C" void kernel_launch(void* const* d_in, const int* in_sizes, int n_in,
                              void* d_out, int out_size)
{
    const float* pot   = (const float*)d_in[0];   // (B,T,K) f32
    const float* trans = (const float*)d_in[1];   // (K,K)   f32
    const int*   lens  = (const int*)  d_in[2];   // (B,)    i32
    float* out = (float*)d_out;                   // (B,T,K) f32

    const int smem = (KK * TRP + 3 * KK) * (int)sizeof(float);   // 69,120 B
    cudaFuncSetAttribute(crf_kernel, cudaFuncAttributeMaxDynamicSharedMemorySize, smem);

    order_kernel<<<1, BB>>>(lens);
    crf_kernel<<<BB, 256, smem>>>(pot, trans, lens, out);
}

// round 5
// speedup vs baseline: 1.4888x; 1.3381x over previous
#include <cuda_runtime.h>
#include <cfloat>

#define BB 256
#define TT 512
#define KK 128
#define TRP 132   // padded transposed-transitions row stride (floats)

// Scratch (__device__ globals only — no runtime allocation)
__device__ float g_states[(size_t)BB * TT * KK];   // 64 MiB Viterbi states
__device__ int   g_order[BB];                      // bid -> batch

// ---------------------------------------------------------------------------
// Rank batches by descending length; bid r (r<148) and bid 403-r land on the
// same SM under the classic placement: long batches pair with short ones.
// ---------------------------------------------------------------------------
__global__ void order_kernel(const int* __restrict__ lens)
{
    __shared__ int sl[BB];
    const int b = threadIdx.x;
    sl[b] = lens[b];
    __syncthreads();
    const int L = sl[b];
    int r = 0;
    #pragma unroll 8
    for (int i = 0; i < BB; ++i) {
        int Li = sl[i];
        r += (Li > L) || (Li == L && i < b);
    }
    g_order[(r < 148) ? r : (403 - r)] = b;
}

// ---------------------------------------------------------------------------
// Packed f32x2 helpers (sm_103a)
// ---------------------------------------------------------------------------
__device__ __forceinline__ unsigned long long addx2(unsigned long long a,
                                                    unsigned long long b) {
    unsigned long long r;
    asm("add.rn.f32x2 %0, %1, %2;" : "=l"(r) : "l"(a), "l"(b));
    return r;
}
__device__ __forceinline__ float2 unpk(unsigned long long v) {
    float2 r;
    asm("mov.b64 {%0, %1}, %2;" : "=f"(r.x), "=f"(r.y) : "l"(v));
    return r;
}
__device__ __forceinline__ unsigned long long pk(float lo, float hi) {
    unsigned long long r;
    asm("mov.b64 %0, {%1, %2};" : "=l"(r) : "f"(lo), "f"(hi));
    return r;
}

// ---------------------------------------------------------------------------
// Backtrace helpers (warp-uniform argmax, first-index tie-break)
// ---------------------------------------------------------------------------
__device__ __forceinline__ unsigned redux_max_u32(unsigned v) {
    unsigned r;
    asm("redux.sync.max.u32 %0, %1, 0xffffffff;" : "=r"(r) : "r"(v));
    return r;
}
__device__ __forceinline__ unsigned redux_min_u32(unsigned v) {
    unsigned r;
    asm("redux.sync.min.u32 %0, %1, 0xffffffff;" : "=r"(r) : "r"(v));
    return r;
}
__device__ __forceinline__ unsigned fkey(float f) {
    unsigned u = __float_as_uint(f);
    return u ^ ((unsigned)((int)u >> 31) | 0x80000000u);
}
__device__ __forceinline__ int argmax128(float4 v, int l)
{
    unsigned k0 = fkey(v.x), k1 = fkey(v.y), k2 = fkey(v.z), k3 = fkey(v.w);
    unsigned km = max(max(k0, k1), max(k2, k3));
    unsigned M  = redux_max_u32(km);
    unsigned il = 0xFFFFFFFFu;
    if (k3 == M) il = 4 * l + 3;
    if (k2 == M) il = 4 * l + 2;
    if (k1 == M) il = 4 * l + 1;
    if (k0 == M) il = 4 * l + 0;
    return (int)redux_min_u32(il);
}

__device__ __forceinline__ void bt_step(float4 cur, const float* __restrict__ s_tr,
                                        int& tag, float* __restrict__ outrow,
                                        int l, bool addtr)
{
    if (addtr) {
        float4 tc = *reinterpret_cast<const float4*>(&s_tr[tag * TRP + 4 * l]);
        cur.x += tc.x; cur.y += tc.y; cur.z += tc.z; cur.w += tc.w;
    }
    tag = argmax128(cur, l);
    float4 r;
    r.x = (4 * l + 0 == tag) ? 1.0f : 0.0f;
    r.y = (4 * l + 1 == tag) ? 1.0f : 0.0f;
    r.z = (4 * l + 2 == tag) ? 1.0f : 0.0f;
    r.w = (4 * l + 3 == tag) ? 1.0f : 0.0f;
    reinterpret_cast<float4*>(outrow)[l] = r;
}

// ---------------------------------------------------------------------------
// Fused Viterbi: one CTA = one batch, 128 threads. Thread j owns output tag j;
// full transitions column j in packed f32x2 registers. Depth-4 prefetch ring
// keeps the pot load off the per-step critical path.
// ---------------------------------------------------------------------------
__global__ void __launch_bounds__(128, 2) crf_kernel(
    const float* __restrict__ pot,
    const float* __restrict__ trans,
    const int*   __restrict__ lens,
    float*       __restrict__ out)
{
    extern __shared__ float sm[];
    float* s_tr = sm;                  // KK*TRP: transposed transitions
    float* s_st = sm + KK * TRP;       // 2*KK ping-pong state

    const int j = threadIdx.x;
    const int b = g_order[blockIdx.x];
    const int len = lens[b];
    const size_t base = (size_t)b * TT * KK;

    // Transitions column j -> 64 packed u64 registers; also stage the
    // transposed copy in smem for the backtrace.
    unsigned long long ad[64];
    #pragma unroll
    for (int q = 0; q < 32; ++q) {
        float v0 = trans[(4 * q + 0) * KK + j];
        float v1 = trans[(4 * q + 1) * KK + j];
        float v2 = trans[(4 * q + 2) * KK + j];
        float v3 = trans[(4 * q + 3) * KK + j];
        ad[2 * q + 0] = pk(v0, v1);
        ad[2 * q + 1] = pk(v2, v3);
        *reinterpret_cast<float4*>(&s_tr[j * TRP + 4 * q]) =
            make_float4(v0, v1, v2, v3);
    }

    float s0 = pot[base + j];
    s_st[j] = s0;
    g_states[base + j] = s0;

    // Depth-4 prefetch ring for the emission potentials.
    const int lm1 = len - 1;
    float xr[4];
    #pragma unroll
    for (int d = 0; d < 4; ++d) {
        int tt = (1 + d < lm1) ? (1 + d) : lm1;
        xr[d] = (len > 1) ? pot[base + (size_t)tt * KK + j] : 0.0f;
    }
    __syncthreads();

    // ---- forward Viterbi ----
    int p = 0;
    #pragma unroll 4
    for (int t = 1; t < len; ++t) {
        float x = xr[(t - 1) & 3];
        int tn = (t + 4 < lm1) ? (t + 4) : lm1;
        xr[(t - 1) & 3] = pot[base + (size_t)tn * KK + j];  // prefetch t+4

        const ulonglong2* sp = reinterpret_cast<const ulonglong2*>(s_st + p * KK);
        float m0 = -FLT_MAX, m1 = -FLT_MAX, m2 = -FLT_MAX, m3 = -FLT_MAX;
        float m4 = -FLT_MAX, m5 = -FLT_MAX, m6 = -FLT_MAX, m7 = -FLT_MAX;
        #pragma unroll
        for (int q = 0; q < 32; q += 2) {
            ulonglong2 sa = sp[q];                          // broadcast LDS.128
            float2 u0 = unpk(addx2(sa.x, ad[2 * q + 0]));
            float2 u1 = unpk(addx2(sa.y, ad[2 * q + 1]));
            m0 = fmaxf(m0, u0.x);
            m1 = fmaxf(m1, u0.y);
            m2 = fmaxf(m2, u1.x);
            m3 = fmaxf(m3, u1.y);
            ulonglong2 sb = sp[q + 1];
            float2 u2 = unpk(addx2(sb.x, ad[2 * q + 2]));
            float2 u3 = unpk(addx2(sb.y, ad[2 * q + 3]));
            m4 = fmaxf(m4, u2.x);
            m5 = fmaxf(m5, u2.y);
            m6 = fmaxf(m6, u3.x);
            m7 = fmaxf(m7, u3.y);
        }
        float ma = fmaxf(fmaxf(m0, m1), fmaxf(m2, m3));
        float mb = fmaxf(fmaxf(m4, m5), fmaxf(m6, m7));
        float ns = x + fmaxf(ma, mb);

        s_st[(p ^ 1) * KK + j] = ns;
        g_states[base + (size_t)t * KK + j] = ns;
        __syncthreads();
        p ^= 1;
    }

    // ---- epilogue: warp 0 backtraces; warps 1-3 write tag-0 rows >= len ----
    const int w = j >> 5;
    const int l = j & 31;

    if (w != 0) {
        const int total = (TT - len) * 32;
        for (int idx = (w - 1) * 32 + l; idx < total; idx += 96) {
            int r = len + (idx >> 5);
            int c = idx & 31;
            float4 v = make_float4(c == 0 ? 1.0f : 0.0f, 0.0f, 0.0f, 0.0f);
            reinterpret_cast<float4*>(out + base + (size_t)r * KK)[c] = v;
        }
        return;
    }

    auto LDst = [&](int t) -> float4 {
        if (t < 0) return make_float4(0.f, 0.f, 0.f, 0.f);
        return reinterpret_cast<const float4*>(&g_states[base + (size_t)t * KK])[l];
    };
    float* const ob = out + base;

    int tag = 0;
    float4 c0 = LDst(len - 1);
    int t = len - 2;
    float4 p0 = LDst(t), p1 = LDst(t - 1), p2 = LDst(t - 2), p3 = LDst(t - 3);

    bt_step(c0, s_tr, tag, ob + (size_t)(len - 1) * KK, l, false);

    while (t >= 3) {
        bt_step(p0, s_tr, tag, ob + (size_t)(t    ) * KK, l, true);  p0 = LDst(t - 4);
        bt_step(p1, s_tr, tag, ob + (size_t)(t - 1) * KK, l, true);  p1 = LDst(t - 5);
        bt_step(p2, s_tr, tag, ob + (size_t)(t - 2) * KK, l, true);  p2 = LDst(t - 6);
        bt_step(p3, s_tr, tag, ob + (size_t)(t - 3) * KK, l, true);  p3 = LDst(t - 7);
        t -= 4;
    }
    if (t >= 0) bt_step(p0, s_tr, tag, ob + (size_t)(t    ) * KK, l, true);
    if (t >= 1) bt_step(p1, s_tr, tag, ob + (size_t)(t - 1) * KK, l, true);
    if (t >= 2) bt_step(p2, s_tr, tag, ob + (size_t)(t - 2) * KK, l, true);
}

// ---------------------------------------------------------------------------
extern "C" void kernel_launch(void* const* d_in, const int* in_sizes, int n_in,
                              void* d_out, int out_size)
{
    const float* pot   = (const float*)d_in[0];   // (B,T,K) f32
    const float* trans = (const float*)d_in[1];   // (K,K)   f32
    const int*   lens  = (const int*)  d_in[2];   // (B,)    i32
    float* out = (float*)d_out;                   // (B,T,K) f32

    const int smem = (KK * TRP + 2 * KK) * (int)sizeof(float);   // 68,608 B
    cudaFuncSetAttribute(crf_kernel, cudaFuncAttributeMaxDynamicSharedMemorySize, smem);

    order_kernel<<<1, BB>>>(lens);
    crf_kernel<<<BB, 128, smem>>>(pot, trans, lens, out);
}